// round 10
// baseline (speedup 1.0000x reference)
#include <cuda_runtime.h>
#include <cuda_fp16.h>
#include <math.h>
#include <cstdint>

#define B_   2
#define T_   2048
#define C_   1024
#define NH   16
#define NKV  4
#define HD   64
#define ROWS (B_ * T_)          // 4096
#define QKVC 1536               // 1024 q + 256 k + 256 v

// ------------------------- scratch (__device__ globals) ---------------------
__device__ float  g_qkv[(size_t)ROWS * QKVC];     // fused qkv, fp32
__device__ __half g_xh[(size_t)ROWS * C_];        // x in fp16
__device__ __half g_wqkv[(size_t)QKVC * C_];      // packed Wq|Wk|Wv fp16
__device__ __half g_wo[(size_t)C_ * C_];          // Wo fp16
__device__ __half g_yh[(size_t)ROWS * C_];        // attention output fp16
__device__ __half g_q16[(size_t)B_ * NH * T_ * HD];   // [b][h][t][d]
__device__ __half g_k16[(size_t)B_ * NKV * T_ * HD];  // [b][hkv][t][d]
__device__ __half g_v16[(size_t)B_ * NKV * T_ * HD];  // [b][hkv][t][d]

// ------------------------------ PTX helpers --------------------------------
__device__ __forceinline__ uint32_t smem_u32(const void* p) {
    uint32_t a;
    asm("{ .reg .u64 t; cvta.to.shared.u64 t, %1; cvt.u32.u64 %0, t; }" : "=r"(a) : "l"(p));
    return a;
}
#define CP16(dst, src) asm volatile("cp.async.cg.shared.global [%0], [%1], 16;" :: "r"(dst), "l"(src) : "memory")
#define CP_COMMIT()    asm volatile("cp.async.commit_group;" ::: "memory")
#define CP_WAIT(n)     asm volatile("cp.async.wait_group %0;" :: "n"(n) : "memory")

__device__ __forceinline__ void ldm_x4(uint32_t& r0, uint32_t& r1, uint32_t& r2, uint32_t& r3,
                                       uint32_t addr) {
    asm volatile("ldmatrix.sync.aligned.m8n8.x4.shared.b16 {%0,%1,%2,%3}, [%4];"
                 : "=r"(r0), "=r"(r1), "=r"(r2), "=r"(r3) : "r"(addr));
}
__device__ __forceinline__ void ldm_x4_t(uint32_t& r0, uint32_t& r1, uint32_t& r2, uint32_t& r3,
                                         uint32_t addr) {
    asm volatile("ldmatrix.sync.aligned.m8n8.x4.trans.shared.b16 {%0,%1,%2,%3}, [%4];"
                 : "=r"(r0), "=r"(r1), "=r"(r2), "=r"(r3) : "r"(addr));
}
__device__ __forceinline__ void mma16816(float& c0, float& c1, float& c2, float& c3,
                                         uint32_t a0, uint32_t a1, uint32_t a2, uint32_t a3,
                                         uint32_t b0, uint32_t b1) {
    asm volatile("mma.sync.aligned.m16n8k16.row.col.f32.f16.f16.f32 "
                 "{%0,%1,%2,%3}, {%4,%5,%6,%7}, {%8,%9}, {%0,%1,%2,%3};"
                 : "+f"(c0), "+f"(c1), "+f"(c2), "+f"(c3)
                 : "r"(a0), "r"(a1), "r"(a2), "r"(a3), "r"(b0), "r"(b1));
}

// GEMM tile: 128 rows x 32 halves (4 chunks/row). chunk ^= (row>>1)&3.
__device__ __forceinline__ uint32_t tile_addr(uint32_t base, int r, int c) {
    return base + (uint32_t)(r * 64) + (uint32_t)((c ^ ((r >> 1) & 3)) * 16);
}
// Attention tile: rows of 64 halves (8 chunks of 16B). chunk ^= row&7.
__device__ __forceinline__ uint32_t addr8(uint32_t base, int r, int c) {
    return base + (uint32_t)(r * 128) + (uint32_t)((c ^ (r & 7)) * 16);
}

// ---------------------------------------------------------------------------
// HMMA fp16 GEMM: C[M,N] = A[M,K] * B[N,K]^T, fp32 out. (validated R6/R7 form)
// BM=BN=128, BK=32, 256 threads, 8 warps (2x4), warp tile 64x32, 2-stage.
// ---------------------------------------------------------------------------
__global__ void __launch_bounds__(256) gemm_mma(
    const __half* __restrict__ A, const __half* __restrict__ Bm,
    float* __restrict__ C, int N, int K)
{
    __shared__ __half As[2][128 * 32];
    __shared__ __half Bs[2][128 * 32];

    const int tid = threadIdx.x;
    const int lane = tid & 31;
    const int wid = tid >> 5;
    const int wm = wid >> 2;
    const int wn = wid & 3;

    const size_t rowBase = (size_t)blockIdx.x * 128;
    const size_t colBase = (size_t)blockIdx.y * 128;
    const __half* Ab = A + rowBase * K;
    const __half* Bb = Bm + colBase * K;

    const uint32_t sa[2] = { smem_u32(As[0]), smem_u32(As[1]) };
    const uint32_t sbm[2] = { smem_u32(Bs[0]), smem_u32(Bs[1]) };

    float acc[4][4][4];
#pragma unroll
    for (int i = 0; i < 4; i++)
#pragma unroll
        for (int j = 0; j < 4; j++)
#pragma unroll
            for (int q = 0; q < 4; q++) acc[i][j][q] = 0.f;

    const int nk = K >> 5;

    const int lg = lane >> 3;
    const int lr = lane & 7;
    const int a_row_off = (lg & 1) * 8 + lr;
    const int a_chunk_off = lg >> 1;
    const int b_row_off = (lg >> 1) * 8 + lr;
    const int b_chunk_off = lg & 1;

    {
#pragma unroll
        for (int i = 0; i < 2; i++) {
            int idx = tid + 256 * i;
            int r = idx >> 2, c = idx & 3;
            CP16(tile_addr(sa[0], r, c),  Ab + (size_t)r * K + c * 8);
            CP16(tile_addr(sbm[0], r, c), Bb + (size_t)r * K + c * 8);
        }
        CP_COMMIT();
    }

    for (int kt = 0; kt < nk; kt++) {
        const int cur = kt & 1;
        if (kt + 1 < nk) {
            const int nxt = cur ^ 1;
            const __half* Abt = Ab + (kt + 1) * 32;
            const __half* Bbt = Bb + (kt + 1) * 32;
#pragma unroll
            for (int i = 0; i < 2; i++) {
                int idx = tid + 256 * i;
                int r = idx >> 2, c = idx & 3;
                CP16(tile_addr(sa[nxt], r, c),  Abt + (size_t)r * K + c * 8);
                CP16(tile_addr(sbm[nxt], r, c), Bbt + (size_t)r * K + c * 8);
            }
            CP_COMMIT();
            CP_WAIT(1);
        } else {
            CP_WAIT(0);
        }
        __syncthreads();

#pragma unroll
        for (int ks = 0; ks < 2; ks++) {
            uint32_t af[4][4];
#pragma unroll
            for (int mi = 0; mi < 4; mi++) {
                int row = wm * 64 + mi * 16 + a_row_off;
                int chunk = 2 * ks + a_chunk_off;
                ldm_x4(af[mi][0], af[mi][1], af[mi][2], af[mi][3],
                       tile_addr(sa[cur], row, chunk));
            }
            uint32_t bf[4][2];
#pragma unroll
            for (int nj2 = 0; nj2 < 2; nj2++) {
                int row = wn * 32 + nj2 * 16 + b_row_off;
                int chunk = 2 * ks + b_chunk_off;
                uint32_t t0, t1, t2, t3;
                ldm_x4(t0, t1, t2, t3, tile_addr(sbm[cur], row, chunk));
                bf[nj2 * 2][0] = t0; bf[nj2 * 2][1] = t1;
                bf[nj2 * 2 + 1][0] = t2; bf[nj2 * 2 + 1][1] = t3;
            }
#pragma unroll
            for (int mi = 0; mi < 4; mi++)
#pragma unroll
                for (int nj = 0; nj < 4; nj++)
                    mma16816(acc[mi][nj][0], acc[mi][nj][1], acc[mi][nj][2], acc[mi][nj][3],
                             af[mi][0], af[mi][1], af[mi][2], af[mi][3],
                             bf[nj][0], bf[nj][1]);
        }
        __syncthreads();
    }

    const int mrow = lane >> 2;
    const int ncol = (lane & 3) * 2;
#pragma unroll
    for (int mi = 0; mi < 4; mi++) {
#pragma unroll
        for (int nj = 0; nj < 4; nj++) {
            size_t r1 = rowBase + wm * 64 + mi * 16 + mrow;
            size_t cc = colBase + wn * 32 + nj * 8 + ncol;
            float2 v0 = make_float2(acc[mi][nj][0], acc[mi][nj][1]);
            float2 v1 = make_float2(acc[mi][nj][2], acc[mi][nj][3]);
            *(float2*)(C + r1 * N + cc) = v0;
            *(float2*)(C + (r1 + 8) * N + cc) = v1;
        }
    }
}

// ---------------------------------------------------------------------------
__global__ void f2h(const float* __restrict__ src, __half* __restrict__ dst, int n4)
{
    int i = blockIdx.x * blockDim.x + threadIdx.x;
    if (i >= n4) return;
    float4 v = ((const float4*)src)[i];
    __half2 h0 = __floats2half2_rn(v.x, v.y);
    __half2 h1 = __floats2half2_rn(v.z, v.w);
    uint2 o; o.x = *(uint32_t*)&h0; o.y = *(uint32_t*)&h1;
    ((uint2*)dst)[i] = o;
}

__global__ void pack_w(const float* __restrict__ Wq, const float* __restrict__ Wk,
                       const float* __restrict__ Wv)
{
    int i = blockIdx.x * blockDim.x + threadIdx.x;
    if (i >= QKVC * C_ / 4) return;
    int row = i >> 8;
    int c4 = i & 255;
    const float* src;
    if (row < 1024)      src = Wq + (size_t)row * C_;
    else if (row < 1280) src = Wk + (size_t)(row - 1024) * C_;
    else                 src = Wv + (size_t)(row - 1280) * C_;
    float4 v = ((const float4*)src)[c4];
    __half2 h0 = __floats2half2_rn(v.x, v.y);
    __half2 h1 = __floats2half2_rn(v.z, v.w);
    uint2 o; o.x = *(uint32_t*)&h0; o.y = *(uint32_t*)&h1;
    ((uint2*)(g_wqkv + (size_t)row * C_))[c4] = o;
}

// ---------------------------------------------------------------------------
// RoPE + RMSNorm from g_qkv (fp32) -> fp16 head-major buffers.
// ---------------------------------------------------------------------------
__global__ void rope_rms_cvt(const float* __restrict__ cosb, const float* __restrict__ sinb)
{
    int gwarp = (blockIdx.x * blockDim.x + threadIdx.x) >> 5;
    int lane = threadIdx.x & 31;
    const int total = ROWS * 24;
    if (gwarp >= total) return;

    int row = gwarp / 24;
    int u   = gwarp % 24;
    int b = row >> 11;
    int t = row & (T_ - 1);

    const float* src;
    __half* dst;
    bool do_rope;
    if (u < NH) {
        src = g_qkv + (size_t)row * QKVC + u * HD;
        dst = g_q16 + ((size_t)(b * NH + u) * T_ + t) * HD;
        do_rope = true;
    } else if (u < NH + NKV) {
        int hk = u - NH;
        src = g_qkv + (size_t)row * QKVC + 1024 + hk * HD;
        dst = g_k16 + ((size_t)(b * NKV + hk) * T_ + t) * HD;
        do_rope = true;
    } else {
        int hv = u - NH - NKV;
        src = g_qkv + (size_t)row * QKVC + 1280 + hv * HD;
        dst = g_v16 + ((size_t)(b * NKV + hv) * T_ + t) * HD;
        do_rope = false;
    }

    float x1 = src[lane];
    float x2 = src[lane + 32];
    float o1, o2;
    if (do_rope) {
        float c = cosb[t * 32 + lane];
        float s = sinb[t * 32 + lane];
        o1 =  x1 * c + x2 * s;
        o2 = -x1 * s + x2 * c;
        float ss = o1 * o1 + o2 * o2;
#pragma unroll
        for (int off = 16; off; off >>= 1)
            ss += __shfl_xor_sync(0xFFFFFFFFu, ss, off);
        float r = rsqrtf(ss * (1.0f / 64.0f) + 1.1920928955078125e-07f);
        o1 *= r; o2 *= r;
    } else {
        o1 = x1; o2 = x2;
    }
    dst[lane]      = __float2half_rn(o1);
    dst[lane + 32] = __float2half_rn(o2);
}

// ---------------------------------------------------------------------------
// HMMA causal GQA flash attention (R7 config + double-buffered KV).
// grid = (T/64, B*NH), block = 128 (4 warps); warp = 16 query rows.
// Per iteration: 64 keys. KV tile i+1 prefetched while computing tile i.
// ---------------------------------------------------------------------------
__global__ void __launch_bounds__(128) flash_mma()
{
    __shared__ __half Qs[64 * 64];        // 8 KB
    __shared__ __half Ks[2][64 * 64];     // 16 KB
    __shared__ __half Vs[2][64 * 64];     // 16 KB

    const int tid = threadIdx.x;
    const int lane = tid & 31;
    const int wid = tid >> 5;

    const int bh = blockIdx.y;
    const int b = bh >> 4;
    const int h = bh & 15;
    const int hkv = h >> 2;
    const int qt = blockIdx.x * 64;

    const __half* qg = g_q16 + ((size_t)(b * NH + h) * T_ + qt) * HD;
    const __half* kg = g_k16 + ((size_t)(b * NKV + hkv) * T_) * HD;
    const __half* vg = g_v16 + ((size_t)(b * NKV + hkv) * T_) * HD;

    const uint32_t sq = smem_u32(Qs);
    const uint32_t sk[2] = { smem_u32(Ks[0]), smem_u32(Ks[1]) };
    const uint32_t sv[2] = { smem_u32(Vs[0]), smem_u32(Vs[1]) };

    // prologue: Q tile + KV tile 0, single commit group
    {
#pragma unroll
        for (int i = 0; i < 4; i++) {
            int idx = tid + 128 * i;      // 0..511
            int r = idx >> 3, c = idx & 7;
            CP16(addr8(sq, r, c), qg + (size_t)r * HD + c * 8);
            CP16(addr8(sk[0], r, c), kg + (size_t)r * HD + c * 8);
            CP16(addr8(sv[0], r, c), vg + (size_t)r * HD + c * 8);
        }
        CP_COMMIT();
    }

    const int lg = lane >> 3;
    const int lr = lane & 7;
    const int a_row = wid * 16 + (lg & 1) * 8 + lr;   // within Q tile
    const int a_chk = lg >> 1;
    const int b_row = (lg >> 1) * 8 + lr;             // + nb*16 for K
    const int b_chk = lg & 1;                         // + 2*ks
    const int v_row = (lg & 1) * 8 + lr;              // + ks*16 for V (trans)
    const int v_chk = lg >> 1;                        // + 2*jd

    uint32_t aq[4][4];

    float oacc[8][4];
#pragma unroll
    for (int i = 0; i < 8; i++)
#pragma unroll
        for (int j = 0; j < 4; j++) oacc[i][j] = 0.f;

    float mrow0 = -1e30f, mrow1 = -1e30f;
    float lrow0 = 0.f, lrow1 = 0.f;

    const int row_lo = qt + wid * 16 + (lane >> 2);
    const int row_hi = row_lo + 8;
    const float sc = 0.125f;          // 1/sqrt(64)

    for (int kv0 = 0; kv0 <= qt; kv0 += 64) {
        const int cur = (kv0 >> 6) & 1;
        CP_WAIT(0);
        __syncthreads();

        if (kv0 == 0) {
#pragma unroll
            for (int ks = 0; ks < 4; ks++)
                ldm_x4(aq[ks][0], aq[ks][1], aq[ks][2], aq[ks][3],
                       addr8(sq, a_row, 2 * ks + a_chk));
        }

        // prefetch next KV tile into the other buffer
        if (kv0 + 64 <= qt) {
            const int nxt = cur ^ 1;
            const __half* kgt = kg + (size_t)(kv0 + 64) * HD;
            const __half* vgt = vg + (size_t)(kv0 + 64) * HD;
#pragma unroll
            for (int i = 0; i < 4; i++) {
                int idx = tid + 128 * i;
                int r = idx >> 3, c = idx & 7;
                CP16(addr8(sk[nxt], r, c), kgt + (size_t)r * HD + c * 8);
                CP16(addr8(sv[nxt], r, c), vgt + (size_t)r * HD + c * 8);
            }
        }
        CP_COMMIT();

        // ---- S = Q K^T ----
        float sacc[8][4];
#pragma unroll
        for (int i = 0; i < 8; i++)
#pragma unroll
            for (int j = 0; j < 4; j++) sacc[i][j] = 0.f;

#pragma unroll
        for (int ks = 0; ks < 4; ks++) {
            uint32_t bf[8][2];
#pragma unroll
            for (int j = 0; j < 4; j++) {
                uint32_t t0, t1, t2, t3;
                ldm_x4(t0, t1, t2, t3, addr8(sk[cur], j * 16 + b_row, 2 * ks + b_chk));
                bf[2 * j][0] = t0; bf[2 * j][1] = t1;
                bf[2 * j + 1][0] = t2; bf[2 * j + 1][1] = t3;
            }
#pragma unroll
            for (int nb = 0; nb < 8; nb++)
                mma16816(sacc[nb][0], sacc[nb][1], sacc[nb][2], sacc[nb][3],
                         aq[ks][0], aq[ks][1], aq[ks][2], aq[ks][3],
                         bf[nb][0], bf[nb][1]);
        }

        // ---- online softmax ----
        const bool diag = (kv0 == qt);
        float mx0 = -1e30f, mx1 = -1e30f;
#pragma unroll
        for (int nb = 0; nb < 8; nb++) {
            float c0 = sacc[nb][0] * sc, c1 = sacc[nb][1] * sc;
            float c2 = sacc[nb][2] * sc, c3 = sacc[nb][3] * sc;
            if (diag) {
                int col = kv0 + nb * 8 + (lane & 3) * 2;
                if (col > row_lo)     c0 = -1e30f;
                if (col + 1 > row_lo) c1 = -1e30f;
                if (col > row_hi)     c2 = -1e30f;
                if (col + 1 > row_hi) c3 = -1e30f;
            }
            sacc[nb][0] = c0; sacc[nb][1] = c1; sacc[nb][2] = c2; sacc[nb][3] = c3;
            mx0 = fmaxf(mx0, fmaxf(c0, c1));
            mx1 = fmaxf(mx1, fmaxf(c2, c3));
        }
        mx0 = fmaxf(mx0, __shfl_xor_sync(0xFFFFFFFFu, mx0, 1));
        mx0 = fmaxf(mx0, __shfl_xor_sync(0xFFFFFFFFu, mx0, 2));
        mx1 = fmaxf(mx1, __shfl_xor_sync(0xFFFFFFFFu, mx1, 1));
        mx1 = fmaxf(mx1, __shfl_xor_sync(0xFFFFFFFFu, mx1, 2));

        float mn0 = fmaxf(mrow0, mx0), mn1 = fmaxf(mrow1, mx1);
        float cor0 = __expf(mrow0 - mn0), cor1 = __expf(mrow1 - mn1);
        mrow0 = mn0; mrow1 = mn1;

        float sum0 = 0.f, sum1 = 0.f;
        uint32_t ph[8][2];
#pragma unroll
        for (int nb = 0; nb < 8; nb++) {
            float p0 = __expf(sacc[nb][0] - mn0);
            float p1 = __expf(sacc[nb][1] - mn0);
            float p2 = __expf(sacc[nb][2] - mn1);
            float p3 = __expf(sacc[nb][3] - mn1);
            sum0 += p0 + p1; sum1 += p2 + p3;
            __half2 h0 = __floats2half2_rn(p0, p1);
            __half2 h1 = __floats2half2_rn(p2, p3);
            ph[nb][0] = *(uint32_t*)&h0;
            ph[nb][1] = *(uint32_t*)&h1;
        }
        lrow0 = lrow0 * cor0 + sum0;
        lrow1 = lrow1 * cor1 + sum1;
#pragma unroll
        for (int nd = 0; nd < 8; nd++) {
            oacc[nd][0] *= cor0; oacc[nd][1] *= cor0;
            oacc[nd][2] *= cor1; oacc[nd][3] *= cor1;
        }

        // ---- O += P V ----
#pragma unroll
        for (int ks = 0; ks < 4; ks++) {
            uint32_t vf[8][2];
#pragma unroll
            for (int jd = 0; jd < 4; jd++) {
                uint32_t t0, t1, t2, t3;
                ldm_x4_t(t0, t1, t2, t3, addr8(sv[cur], ks * 16 + v_row, 2 * jd + v_chk));
                vf[2 * jd][0] = t0; vf[2 * jd][1] = t1;
                vf[2 * jd + 1][0] = t2; vf[2 * jd + 1][1] = t3;
            }
#pragma unroll
            for (int nd = 0; nd < 8; nd++)
                mma16816(oacc[nd][0], oacc[nd][1], oacc[nd][2], oacc[nd][3],
                         ph[2 * ks][0], ph[2 * ks][1], ph[2 * ks + 1][0], ph[2 * ks + 1][1],
                         vf[nd][0], vf[nd][1]);
        }
    }

    // final: reduce l across quad, normalize, store fp16
    lrow0 += __shfl_xor_sync(0xFFFFFFFFu, lrow0, 1);
    lrow0 += __shfl_xor_sync(0xFFFFFFFFu, lrow0, 2);
    lrow1 += __shfl_xor_sync(0xFFFFFFFFu, lrow1, 1);
    lrow1 += __shfl_xor_sync(0xFFFFFFFFu, lrow1, 2);
    float inv0 = 1.f / lrow0, inv1 = 1.f / lrow1;

#pragma unroll
    for (int nd = 0; nd < 8; nd++) {
        int col = nd * 8 + (lane & 3) * 2;
        __half* y0 = g_yh + ((size_t)(b * T_ + row_lo)) * C_ + h * HD + col;
        __half* y1 = g_yh + ((size_t)(b * T_ + row_hi)) * C_ + h * HD + col;
        __half2 h0 = __floats2half2_rn(oacc[nd][0] * inv0, oacc[nd][1] * inv0);
        __half2 h1 = __floats2half2_rn(oacc[nd][2] * inv1, oacc[nd][3] * inv1);
        *(__half2*)y0 = h0;
        *(__half2*)y1 = h1;
    }
}

// ---------------------------------------------------------------------------
extern "C" void kernel_launch(void* const* d_in, const int* in_sizes, int n_in,
                              void* d_out, int out_size)
{
    const float* x    = (const float*)d_in[0];
    const float* cosb = (const float*)d_in[1];
    const float* sinb = (const float*)d_in[2];
    const float* Wq   = (const float*)d_in[3];
    const float* Wk   = (const float*)d_in[4];
    const float* Wv   = (const float*)d_in[5];
    const float* Wo   = (const float*)d_in[6];
    float* out = (float*)d_out;

    float  *qkvp;
    __half *xhp, *wop, *yhp, *wqkvp;
    cudaGetSymbolAddress((void**)&qkvp, g_qkv);
    cudaGetSymbolAddress((void**)&xhp,  g_xh);
    cudaGetSymbolAddress((void**)&wop,  g_wo);
    cudaGetSymbolAddress((void**)&yhp,  g_yh);
    cudaGetSymbolAddress((void**)&wqkvp, g_wqkv);

    // conversions
    { int n4 = ROWS * C_ / 4;  f2h<<<(n4 + 255) / 256, 256>>>(x, xhp, n4); }
    { int n4 = QKVC * C_ / 4;  pack_w<<<(n4 + 255) / 256, 256>>>(Wq, Wk, Wv); }
    { int n4 = C_ * C_ / 4;    f2h<<<(n4 + 255) / 256, 256>>>(Wo, wop, n4); }

    // fused QKV projection: [4096,1536] = xh * wqkv^T
    gemm_mma<<<dim3(ROWS / 128, QKVC / 128), 256>>>(xhp, wqkvp, qkvp, QKVC, C_);

    // RoPE + RMSNorm + fp16 head-major conversion
    {
        int warps = ROWS * 24;
        int threads = warps * 32;
        rope_rms_cvt<<<(threads + 255) / 256, 256>>>(cosb, sinb);
    }

    // HMMA causal flash attention (64-query CTAs, double-buffered KV)
    flash_mma<<<dim3(T_ / 64, B_ * NH), 128>>>();

    // output projection: out[4096,1024] = yh * wo^T
    gemm_mma<<<dim3(ROWS / 128, C_ / 128), 256>>>(yhp, wop, out, C_, C_);
}

// round 14
// speedup vs baseline: 1.5865x; 1.5865x over previous
#include <cuda_runtime.h>
#include <cuda_fp16.h>
#include <math.h>
#include <cstdint>

#define B_   2
#define T_   2048
#define C_   1024
#define NH   16
#define NKV  4
#define HD   64
#define ROWS (B_ * T_)          // 4096
#define QKVC 1536               // 1024 q + 256 k + 256 v

// ------------------------- scratch (__device__ globals) ---------------------
__device__ float  g_qkv[(size_t)ROWS * QKVC];     // fused qkv, fp32
__device__ __half g_xh[(size_t)ROWS * C_];        // x in fp16
__device__ __half g_wqkv[(size_t)QKVC * C_];      // packed Wq|Wk|Wv fp16
__device__ __half g_wo[(size_t)C_ * C_];          // Wo fp16
__device__ __half g_yh[(size_t)ROWS * C_];        // attention output fp16
__device__ __half g_q16[(size_t)B_ * NH * T_ * HD];   // [b][h][t][d]
__device__ __half g_k16[(size_t)B_ * NKV * T_ * HD];  // [b][hkv][t][d]
__device__ __half g_v16[(size_t)B_ * NKV * T_ * HD];  // [b][hkv][t][d]

// ------------------------------ PTX helpers --------------------------------
__device__ __forceinline__ uint32_t smem_u32(const void* p) {
    uint32_t a;
    asm("{ .reg .u64 t; cvta.to.shared.u64 t, %1; cvt.u32.u64 %0, t; }" : "=r"(a) : "l"(p));
    return a;
}
#define CP16(dst, src) asm volatile("cp.async.cg.shared.global [%0], [%1], 16;" :: "r"(dst), "l"(src) : "memory")
#define CP_COMMIT()    asm volatile("cp.async.commit_group;" ::: "memory")
#define CP_WAIT(n)     asm volatile("cp.async.wait_group %0;" :: "n"(n) : "memory")

__device__ __forceinline__ void ldm_x4(uint32_t& r0, uint32_t& r1, uint32_t& r2, uint32_t& r3,
                                       uint32_t addr) {
    asm volatile("ldmatrix.sync.aligned.m8n8.x4.shared.b16 {%0,%1,%2,%3}, [%4];"
                 : "=r"(r0), "=r"(r1), "=r"(r2), "=r"(r3) : "r"(addr));
}
__device__ __forceinline__ void ldm_x4_t(uint32_t& r0, uint32_t& r1, uint32_t& r2, uint32_t& r3,
                                         uint32_t addr) {
    asm volatile("ldmatrix.sync.aligned.m8n8.x4.trans.shared.b16 {%0,%1,%2,%3}, [%4];"
                 : "=r"(r0), "=r"(r1), "=r"(r2), "=r"(r3) : "r"(addr));
}
__device__ __forceinline__ void mma16816(float& c0, float& c1, float& c2, float& c3,
                                         uint32_t a0, uint32_t a1, uint32_t a2, uint32_t a3,
                                         uint32_t b0, uint32_t b1) {
    asm volatile("mma.sync.aligned.m16n8k16.row.col.f32.f16.f16.f32 "
                 "{%0,%1,%2,%3}, {%4,%5,%6,%7}, {%8,%9}, {%0,%1,%2,%3};"
                 : "+f"(c0), "+f"(c1), "+f"(c2), "+f"(c3)
                 : "r"(a0), "r"(a1), "r"(a2), "r"(a3), "r"(b0), "r"(b1));
}

// GEMM tile: 128 rows x 32 halves (4 chunks/row). chunk ^= (row>>1)&3.
__device__ __forceinline__ uint32_t tile_addr(uint32_t base, int r, int c) {
    return base + (uint32_t)(r * 64) + (uint32_t)((c ^ ((r >> 1) & 3)) * 16);
}
// Attention tile: rows of 64 halves (8 chunks of 16B). chunk ^= row&7.
__device__ __forceinline__ uint32_t addr8(uint32_t base, int r, int c) {
    return base + (uint32_t)(r * 128) + (uint32_t)((c ^ (r & 7)) * 16);
}

// ---------------------------------------------------------------------------
// HMMA fp16 GEMM: C[M,N] = A[M,K] * B[N,K]^T, fp32 out. (validated R6/R7 form)
// BM=BN=128, BK=32, 256 threads, 8 warps (2x4), warp tile 64x32, 2-stage.
// ---------------------------------------------------------------------------
__global__ void __launch_bounds__(256) gemm_mma(
    const __half* __restrict__ A, const __half* __restrict__ Bm,
    float* __restrict__ C, int N, int K)
{
    __shared__ __half As[2][128 * 32];
    __shared__ __half Bs[2][128 * 32];

    const int tid = threadIdx.x;
    const int lane = tid & 31;
    const int wid = tid >> 5;
    const int wm = wid >> 2;
    const int wn = wid & 3;

    const size_t rowBase = (size_t)blockIdx.x * 128;
    const size_t colBase = (size_t)blockIdx.y * 128;
    const __half* Ab = A + rowBase * K;
    const __half* Bb = Bm + colBase * K;

    const uint32_t sa[2] = { smem_u32(As[0]), smem_u32(As[1]) };
    const uint32_t sbm[2] = { smem_u32(Bs[0]), smem_u32(Bs[1]) };

    float acc[4][4][4];
#pragma unroll
    for (int i = 0; i < 4; i++)
#pragma unroll
        for (int j = 0; j < 4; j++)
#pragma unroll
            for (int q = 0; q < 4; q++) acc[i][j][q] = 0.f;

    const int nk = K >> 5;

    const int lg = lane >> 3;
    const int lr = lane & 7;
    const int a_row_off = (lg & 1) * 8 + lr;
    const int a_chunk_off = lg >> 1;
    const int b_row_off = (lg >> 1) * 8 + lr;
    const int b_chunk_off = lg & 1;

    {
#pragma unroll
        for (int i = 0; i < 2; i++) {
            int idx = tid + 256 * i;
            int r = idx >> 2, c = idx & 3;
            CP16(tile_addr(sa[0], r, c),  Ab + (size_t)r * K + c * 8);
            CP16(tile_addr(sbm[0], r, c), Bb + (size_t)r * K + c * 8);
        }
        CP_COMMIT();
    }

    for (int kt = 0; kt < nk; kt++) {
        const int cur = kt & 1;
        if (kt + 1 < nk) {
            const int nxt = cur ^ 1;
            const __half* Abt = Ab + (kt + 1) * 32;
            const __half* Bbt = Bb + (kt + 1) * 32;
#pragma unroll
            for (int i = 0; i < 2; i++) {
                int idx = tid + 256 * i;
                int r = idx >> 2, c = idx & 3;
                CP16(tile_addr(sa[nxt], r, c),  Abt + (size_t)r * K + c * 8);
                CP16(tile_addr(sbm[nxt], r, c), Bbt + (size_t)r * K + c * 8);
            }
            CP_COMMIT();
            CP_WAIT(1);
        } else {
            CP_WAIT(0);
        }
        __syncthreads();

#pragma unroll
        for (int ks = 0; ks < 2; ks++) {
            uint32_t af[4][4];
#pragma unroll
            for (int mi = 0; mi < 4; mi++) {
                int row = wm * 64 + mi * 16 + a_row_off;
                int chunk = 2 * ks + a_chunk_off;
                ldm_x4(af[mi][0], af[mi][1], af[mi][2], af[mi][3],
                       tile_addr(sa[cur], row, chunk));
            }
            uint32_t bf[4][2];
#pragma unroll
            for (int nj2 = 0; nj2 < 2; nj2++) {
                int row = wn * 32 + nj2 * 16 + b_row_off;
                int chunk = 2 * ks + b_chunk_off;
                uint32_t t0, t1, t2, t3;
                ldm_x4(t0, t1, t2, t3, tile_addr(sbm[cur], row, chunk));
                bf[nj2 * 2][0] = t0; bf[nj2 * 2][1] = t1;
                bf[nj2 * 2 + 1][0] = t2; bf[nj2 * 2 + 1][1] = t3;
            }
#pragma unroll
            for (int mi = 0; mi < 4; mi++)
#pragma unroll
                for (int nj = 0; nj < 4; nj++)
                    mma16816(acc[mi][nj][0], acc[mi][nj][1], acc[mi][nj][2], acc[mi][nj][3],
                             af[mi][0], af[mi][1], af[mi][2], af[mi][3],
                             bf[nj][0], bf[nj][1]);
        }
        __syncthreads();
    }

    const int mrow = lane >> 2;
    const int ncol = (lane & 3) * 2;
#pragma unroll
    for (int mi = 0; mi < 4; mi++) {
#pragma unroll
        for (int nj = 0; nj < 4; nj++) {
            size_t r1 = rowBase + wm * 64 + mi * 16 + mrow;
            size_t cc = colBase + wn * 32 + nj * 8 + ncol;
            float2 v0 = make_float2(acc[mi][nj][0], acc[mi][nj][1]);
            float2 v1 = make_float2(acc[mi][nj][2], acc[mi][nj][3]);
            *(float2*)(C + r1 * N + cc) = v0;
            *(float2*)(C + (r1 + 8) * N + cc) = v1;
        }
    }
}

// ---------------------------------------------------------------------------
__global__ void f2h(const float* __restrict__ src, __half* __restrict__ dst, int n4)
{
    int i = blockIdx.x * blockDim.x + threadIdx.x;
    if (i >= n4) return;
    float4 v = ((const float4*)src)[i];
    __half2 h0 = __floats2half2_rn(v.x, v.y);
    __half2 h1 = __floats2half2_rn(v.z, v.w);
    uint2 o; o.x = *(uint32_t*)&h0; o.y = *(uint32_t*)&h1;
    ((uint2*)dst)[i] = o;
}

__global__ void pack_w(const float* __restrict__ Wq, const float* __restrict__ Wk,
                       const float* __restrict__ Wv)
{
    int i = blockIdx.x * blockDim.x + threadIdx.x;
    if (i >= QKVC * C_ / 4) return;
    int row = i >> 8;
    int c4 = i & 255;
    const float* src;
    if (row < 1024)      src = Wq + (size_t)row * C_;
    else if (row < 1280) src = Wk + (size_t)(row - 1024) * C_;
    else                 src = Wv + (size_t)(row - 1280) * C_;
    float4 v = ((const float4*)src)[c4];
    __half2 h0 = __floats2half2_rn(v.x, v.y);
    __half2 h1 = __floats2half2_rn(v.z, v.w);
    uint2 o; o.x = *(uint32_t*)&h0; o.y = *(uint32_t*)&h1;
    ((uint2*)(g_wqkv + (size_t)row * C_))[c4] = o;
}

// ---------------------------------------------------------------------------
// RoPE + RMSNorm from g_qkv (fp32) -> fp16 head-major buffers.
// ---------------------------------------------------------------------------
__global__ void rope_rms_cvt(const float* __restrict__ cosb, const float* __restrict__ sinb)
{
    int gwarp = (blockIdx.x * blockDim.x + threadIdx.x) >> 5;
    int lane = threadIdx.x & 31;
    const int total = ROWS * 24;
    if (gwarp >= total) return;

    int row = gwarp / 24;
    int u   = gwarp % 24;
    int b = row >> 11;
    int t = row & (T_ - 1);

    const float* src;
    __half* dst;
    bool do_rope;
    if (u < NH) {
        src = g_qkv + (size_t)row * QKVC + u * HD;
        dst = g_q16 + ((size_t)(b * NH + u) * T_ + t) * HD;
        do_rope = true;
    } else if (u < NH + NKV) {
        int hk = u - NH;
        src = g_qkv + (size_t)row * QKVC + 1024 + hk * HD;
        dst = g_k16 + ((size_t)(b * NKV + hk) * T_ + t) * HD;
        do_rope = true;
    } else {
        int hv = u - NH - NKV;
        src = g_qkv + (size_t)row * QKVC + 1280 + hv * HD;
        dst = g_v16 + ((size_t)(b * NKV + hv) * T_ + t) * HD;
        do_rope = false;
    }

    float x1 = src[lane];
    float x2 = src[lane + 32];
    float o1, o2;
    if (do_rope) {
        float c = cosb[t * 32 + lane];
        float s = sinb[t * 32 + lane];
        o1 =  x1 * c + x2 * s;
        o2 = -x1 * s + x2 * c;
        float ss = o1 * o1 + o2 * o2;
#pragma unroll
        for (int off = 16; off; off >>= 1)
            ss += __shfl_xor_sync(0xFFFFFFFFu, ss, off);
        float r = rsqrtf(ss * (1.0f / 64.0f) + 1.1920928955078125e-07f);
        o1 *= r; o2 *= r;
    } else {
        o1 = x1; o2 = x2;
    }
    dst[lane]      = __float2half_rn(o1);
    dst[lane + 32] = __float2half_rn(o2);
}

// ---------------------------------------------------------------------------
// HMMA causal GQA flash attention (R7 geometry; split K/V waits; heavy first).
// grid = (T/64, B*NH), block = 128 (4 warps); warp = 16 query rows.
// Per iteration: 64 keys. K committed separately from V; V load overlaps S+softmax.
// ---------------------------------------------------------------------------
__global__ void __launch_bounds__(128) flash_mma()
{
    __shared__ __half Qs[64 * 64];
    __shared__ __half Ks[64 * 64];
    __shared__ __half Vs[64 * 64];

    const int tid = threadIdx.x;
    const int lane = tid & 31;
    const int wid = tid >> 5;

    const int bh = blockIdx.y;
    const int b = bh >> 4;
    const int h = bh & 15;
    const int hkv = h >> 2;
    const int qt = (gridDim.x - 1 - blockIdx.x) * 64;   // heavy blocks first

    const __half* qg = g_q16 + ((size_t)(b * NH + h) * T_ + qt) * HD;
    const __half* kg = g_k16 + ((size_t)(b * NKV + hkv) * T_) * HD;
    const __half* vg = g_v16 + ((size_t)(b * NKV + hkv) * T_) * HD;

    const uint32_t sq = smem_u32(Qs), sk = smem_u32(Ks), sv = smem_u32(Vs);

    // stage Q tile (64x64), own commit group
#pragma unroll
    for (int i = 0; i < 4; i++) {
        int idx = tid + 128 * i;      // 0..511
        int r = idx >> 3, c = idx & 7;
        CP16(addr8(sq, r, c), qg + (size_t)r * HD + c * 8);
    }
    CP_COMMIT();

    const int lg = lane >> 3;
    const int lr = lane & 7;
    const int a_row = wid * 16 + (lg & 1) * 8 + lr;   // within Q tile
    const int a_chk = lg >> 1;
    const int b_row = (lg >> 1) * 8 + lr;             // + nb*16 for K
    const int b_chk = lg & 1;                         // + 2*ks
    const int v_row = (lg & 1) * 8 + lr;              // + ks*16 for V (trans)
    const int v_chk = lg >> 1;                        // + 2*jd

    uint32_t aq[4][4];
    bool q_loaded = false;

    float oacc[8][4];
#pragma unroll
    for (int i = 0; i < 8; i++)
#pragma unroll
        for (int j = 0; j < 4; j++) oacc[i][j] = 0.f;

    float mrow0 = -1e30f, mrow1 = -1e30f;
    float lrow0 = 0.f, lrow1 = 0.f;

    const int row_lo = qt + wid * 16 + (lane >> 2);
    const int row_hi = row_lo + 8;
    const float sc = 0.125f;          // 1/sqrt(64)

    for (int kv0 = 0; kv0 <= qt; kv0 += 64) {
        __syncthreads();              // previous iteration done with K/V smem
        // K tile -> group, V tile -> separate group
#pragma unroll
        for (int i = 0; i < 4; i++) {
            int idx = tid + 128 * i;
            int r = idx >> 3, c = idx & 7;
            CP16(addr8(sk, r, c), kg + (size_t)(kv0 + r) * HD + c * 8);
        }
        CP_COMMIT();
#pragma unroll
        for (int i = 0; i < 4; i++) {
            int idx = tid + 128 * i;
            int r = idx >> 3, c = idx & 7;
            CP16(addr8(sv, r, c), vg + (size_t)(kv0 + r) * HD + c * 8);
        }
        CP_COMMIT();

        CP_WAIT(1);                   // Q (first iter) + K complete; V in flight
        __syncthreads();

        if (!q_loaded) {
            q_loaded = true;
#pragma unroll
            for (int ks = 0; ks < 4; ks++)
                ldm_x4(aq[ks][0], aq[ks][1], aq[ks][2], aq[ks][3],
                       addr8(sq, a_row, 2 * ks + a_chk));
        }

        // ---- S = Q K^T ----
        float sacc[8][4];
#pragma unroll
        for (int i = 0; i < 8; i++)
#pragma unroll
            for (int j = 0; j < 4; j++) sacc[i][j] = 0.f;

#pragma unroll
        for (int ks = 0; ks < 4; ks++) {
            uint32_t bf[8][2];
#pragma unroll
            for (int j = 0; j < 4; j++) {
                uint32_t t0, t1, t2, t3;
                ldm_x4(t0, t1, t2, t3, addr8(sk, j * 16 + b_row, 2 * ks + b_chk));
                bf[2 * j][0] = t0; bf[2 * j][1] = t1;
                bf[2 * j + 1][0] = t2; bf[2 * j + 1][1] = t3;
            }
#pragma unroll
            for (int nb = 0; nb < 8; nb++)
                mma16816(sacc[nb][0], sacc[nb][1], sacc[nb][2], sacc[nb][3],
                         aq[ks][0], aq[ks][1], aq[ks][2], aq[ks][3],
                         bf[nb][0], bf[nb][1]);
        }

        // ---- online softmax (V still loading) ----
        const bool diag = (kv0 == qt);
        float mx0 = -1e30f, mx1 = -1e30f;
#pragma unroll
        for (int nb = 0; nb < 8; nb++) {
            float c0 = sacc[nb][0] * sc, c1 = sacc[nb][1] * sc;
            float c2 = sacc[nb][2] * sc, c3 = sacc[nb][3] * sc;
            if (diag) {
                int col = kv0 + nb * 8 + (lane & 3) * 2;
                if (col > row_lo)     c0 = -1e30f;
                if (col + 1 > row_lo) c1 = -1e30f;
                if (col > row_hi)     c2 = -1e30f;
                if (col + 1 > row_hi) c3 = -1e30f;
            }
            sacc[nb][0] = c0; sacc[nb][1] = c1; sacc[nb][2] = c2; sacc[nb][3] = c3;
            mx0 = fmaxf(mx0, fmaxf(c0, c1));
            mx1 = fmaxf(mx1, fmaxf(c2, c3));
        }
        mx0 = fmaxf(mx0, __shfl_xor_sync(0xFFFFFFFFu, mx0, 1));
        mx0 = fmaxf(mx0, __shfl_xor_sync(0xFFFFFFFFu, mx0, 2));
        mx1 = fmaxf(mx1, __shfl_xor_sync(0xFFFFFFFFu, mx1, 1));
        mx1 = fmaxf(mx1, __shfl_xor_sync(0xFFFFFFFFu, mx1, 2));

        float mn0 = fmaxf(mrow0, mx0), mn1 = fmaxf(mrow1, mx1);
        float cor0 = __expf(mrow0 - mn0), cor1 = __expf(mrow1 - mn1);
        mrow0 = mn0; mrow1 = mn1;

        float sum0 = 0.f, sum1 = 0.f;
        uint32_t ph[8][2];
#pragma unroll
        for (int nb = 0; nb < 8; nb++) {
            float p0 = __expf(sacc[nb][0] - mn0);
            float p1 = __expf(sacc[nb][1] - mn0);
            float p2 = __expf(sacc[nb][2] - mn1);
            float p3 = __expf(sacc[nb][3] - mn1);
            sum0 += p0 + p1; sum1 += p2 + p3;
            __half2 h0 = __floats2half2_rn(p0, p1);
            __half2 h1 = __floats2half2_rn(p2, p3);
            ph[nb][0] = *(uint32_t*)&h0;
            ph[nb][1] = *(uint32_t*)&h1;
        }
        lrow0 = lrow0 * cor0 + sum0;
        lrow1 = lrow1 * cor1 + sum1;
#pragma unroll
        for (int nd = 0; nd < 8; nd++) {
            oacc[nd][0] *= cor0; oacc[nd][1] *= cor0;
            oacc[nd][2] *= cor1; oacc[nd][3] *= cor1;
        }

        CP_WAIT(0);                   // V complete
        __syncthreads();

        // ---- O += P V ----
#pragma unroll
        for (int ks = 0; ks < 4; ks++) {
            uint32_t vf[8][2];
#pragma unroll
            for (int jd = 0; jd < 4; jd++) {
                uint32_t t0, t1, t2, t3;
                ldm_x4_t(t0, t1, t2, t3, addr8(sv, ks * 16 + v_row, 2 * jd + v_chk));
                vf[2 * jd][0] = t0; vf[2 * jd][1] = t1;
                vf[2 * jd + 1][0] = t2; vf[2 * jd + 1][1] = t3;
            }
#pragma unroll
            for (int nd = 0; nd < 8; nd++)
                mma16816(oacc[nd][0], oacc[nd][1], oacc[nd][2], oacc[nd][3],
                         ph[2 * ks][0], ph[2 * ks][1], ph[2 * ks + 1][0], ph[2 * ks + 1][1],
                         vf[nd][0], vf[nd][1]);
        }
    }

    // final: reduce l across quad, normalize, store fp16
    lrow0 += __shfl_xor_sync(0xFFFFFFFFu, lrow0, 1);
    lrow0 += __shfl_xor_sync(0xFFFFFFFFu, lrow0, 2);
    lrow1 += __shfl_xor_sync(0xFFFFFFFFu, lrow1, 1);
    lrow1 += __shfl_xor_sync(0xFFFFFFFFu, lrow1, 2);
    float inv0 = 1.f / lrow0, inv1 = 1.f / lrow1;

#pragma unroll
    for (int nd = 0; nd < 8; nd++) {
        int col = nd * 8 + (lane & 3) * 2;
        __half* y0 = g_yh + ((size_t)(b * T_ + row_lo)) * C_ + h * HD + col;
        __half* y1 = g_yh + ((size_t)(b * T_ + row_hi)) * C_ + h * HD + col;
        __half2 h0 = __floats2half2_rn(oacc[nd][0] * inv0, oacc[nd][1] * inv0);
        __half2 h1 = __floats2half2_rn(oacc[nd][2] * inv1, oacc[nd][3] * inv1);
        *(__half2*)y0 = h0;
        *(__half2*)y1 = h1;
    }
}

// ---------------------------------------------------------------------------
extern "C" void kernel_launch(void* const* d_in, const int* in_sizes, int n_in,
                              void* d_out, int out_size)
{
    const float* x    = (const float*)d_in[0];
    const float* cosb = (const float*)d_in[1];
    const float* sinb = (const float*)d_in[2];
    const float* Wq   = (const float*)d_in[3];
    const float* Wk   = (const float*)d_in[4];
    const float* Wv   = (const float*)d_in[5];
    const float* Wo   = (const float*)d_in[6];
    float* out = (float*)d_out;

    float  *qkvp;
    __half *xhp, *wop, *yhp, *wqkvp;
    cudaGetSymbolAddress((void**)&qkvp, g_qkv);
    cudaGetSymbolAddress((void**)&xhp,  g_xh);
    cudaGetSymbolAddress((void**)&wop,  g_wo);
    cudaGetSymbolAddress((void**)&yhp,  g_yh);
    cudaGetSymbolAddress((void**)&wqkvp, g_wqkv);

    // conversions
    { int n4 = ROWS * C_ / 4;  f2h<<<(n4 + 255) / 256, 256>>>(x, xhp, n4); }
    { int n4 = QKVC * C_ / 4;  pack_w<<<(n4 + 255) / 256, 256>>>(Wq, Wk, Wv); }
    { int n4 = C_ * C_ / 4;    f2h<<<(n4 + 255) / 256, 256>>>(Wo, wop, n4); }

    // fused QKV projection: [4096,1536] = xh * wqkv^T
    gemm_mma<<<dim3(ROWS / 128, QKVC / 128), 256>>>(xhp, wqkvp, qkvp, QKVC, C_);

    // RoPE + RMSNorm + fp16 head-major conversion
    {
        int warps = ROWS * 24;
        int threads = warps * 32;
        rope_rms_cvt<<<(threads + 255) / 256, 256>>>(cosb, sinb);
    }

    // HMMA causal flash attention (R7 geometry, split K/V waits)
    flash_mma<<<dim3(T_ / 64, B_ * NH), 128>>>();

    // output projection: out[4096,1024] = yh * wo^T
    gemm_mma<<<dim3(ROWS / 128, C_ / 128), 256>>>(yhp, wop, out, C_, C_);
}

// round 15
// speedup vs baseline: 1.6207x; 1.0216x over previous
#include <cuda_runtime.h>
#include <cuda_fp16.h>
#include <math.h>
#include <cstdint>

#define B_   2
#define T_   2048
#define C_   1024
#define NH   16
#define NKV  4
#define HD   64
#define ROWS (B_ * T_)          // 4096
#define QKVC 1536               // 1024 q + 256 k + 256 v

// ------------------------- scratch (__device__ globals) ---------------------
__device__ __half g_xh[(size_t)ROWS * C_];        // x in fp16
__device__ __half g_wqkv[(size_t)QKVC * C_];      // packed Wq|Wk|Wv fp16
__device__ __half g_wo[(size_t)C_ * C_];          // Wo fp16
__device__ __half g_yh[(size_t)ROWS * C_];        // attention output fp16
__device__ __half g_q16[(size_t)B_ * NH * T_ * HD];   // [b][h][t][d]
__device__ __half g_k16[(size_t)B_ * NKV * T_ * HD];  // [b][hkv][t][d]
__device__ __half g_v16[(size_t)B_ * NKV * T_ * HD];  // [b][hkv][t][d]

// ------------------------------ PTX helpers --------------------------------
__device__ __forceinline__ uint32_t smem_u32(const void* p) {
    uint32_t a;
    asm("{ .reg .u64 t; cvta.to.shared.u64 t, %1; cvt.u32.u64 %0, t; }" : "=r"(a) : "l"(p));
    return a;
}
#define CP16(dst, src) asm volatile("cp.async.cg.shared.global [%0], [%1], 16;" :: "r"(dst), "l"(src) : "memory")
#define CP_COMMIT()    asm volatile("cp.async.commit_group;" ::: "memory")
#define CP_WAIT(n)     asm volatile("cp.async.wait_group %0;" :: "n"(n) : "memory")

__device__ __forceinline__ void ldm_x4(uint32_t& r0, uint32_t& r1, uint32_t& r2, uint32_t& r3,
                                       uint32_t addr) {
    asm volatile("ldmatrix.sync.aligned.m8n8.x4.shared.b16 {%0,%1,%2,%3}, [%4];"
                 : "=r"(r0), "=r"(r1), "=r"(r2), "=r"(r3) : "r"(addr));
}
__device__ __forceinline__ void ldm_x4_t(uint32_t& r0, uint32_t& r1, uint32_t& r2, uint32_t& r3,
                                         uint32_t addr) {
    asm volatile("ldmatrix.sync.aligned.m8n8.x4.trans.shared.b16 {%0,%1,%2,%3}, [%4];"
                 : "=r"(r0), "=r"(r1), "=r"(r2), "=r"(r3) : "r"(addr));
}
__device__ __forceinline__ void mma16816(float& c0, float& c1, float& c2, float& c3,
                                         uint32_t a0, uint32_t a1, uint32_t a2, uint32_t a3,
                                         uint32_t b0, uint32_t b1) {
    asm volatile("mma.sync.aligned.m16n8k16.row.col.f32.f16.f16.f32 "
                 "{%0,%1,%2,%3}, {%4,%5,%6,%7}, {%8,%9}, {%0,%1,%2,%3};"
                 : "+f"(c0), "+f"(c1), "+f"(c2), "+f"(c3)
                 : "r"(a0), "r"(a1), "r"(a2), "r"(a3), "r"(b0), "r"(b1));
}

// GEMM tile: 128 rows x 32 halves (4 chunks/row). chunk ^= (row>>1)&3.
__device__ __forceinline__ uint32_t tile_addr(uint32_t base, int r, int c) {
    return base + (uint32_t)(r * 64) + (uint32_t)((c ^ ((r >> 1) & 3)) * 16);
}
// Attention tile: rows of 64 halves (8 chunks of 16B). chunk ^= row&7.
__device__ __forceinline__ uint32_t addr8(uint32_t base, int r, int c) {
    return base + (uint32_t)(r * 128) + (uint32_t)((c ^ (r & 7)) * 16);
}

// ---------------------------------------------------------------------------
// HMMA fp16 GEMM: C[M,N] = A[M,K] * B[N,K]^T. (validated R6/R7 mainloop)
// BM=BN=128, BK=32, 256 threads, 8 warps (2x4), warp tile 64x32, 2-stage.
// mode 0: fp32 C out. mode 1: scatter fp16 into head-major g_q16/g_k16/g_v16.
// ---------------------------------------------------------------------------
__global__ void __launch_bounds__(256) gemm_mma(
    const __half* __restrict__ A, const __half* __restrict__ Bm,
    float* __restrict__ C, int N, int K, int mode)
{
    __shared__ __half As[2][128 * 32];
    __shared__ __half Bs[2][128 * 32];

    const int tid = threadIdx.x;
    const int lane = tid & 31;
    const int wid = tid >> 5;
    const int wm = wid >> 2;
    const int wn = wid & 3;

    const size_t rowBase = (size_t)blockIdx.x * 128;
    const size_t colBase = (size_t)blockIdx.y * 128;
    const __half* Ab = A + rowBase * K;
    const __half* Bb = Bm + colBase * K;

    const uint32_t sa[2] = { smem_u32(As[0]), smem_u32(As[1]) };
    const uint32_t sbm[2] = { smem_u32(Bs[0]), smem_u32(Bs[1]) };

    float acc[4][4][4];
#pragma unroll
    for (int i = 0; i < 4; i++)
#pragma unroll
        for (int j = 0; j < 4; j++)
#pragma unroll
            for (int q = 0; q < 4; q++) acc[i][j][q] = 0.f;

    const int nk = K >> 5;

    const int lg = lane >> 3;
    const int lr = lane & 7;
    const int a_row_off = (lg & 1) * 8 + lr;
    const int a_chunk_off = lg >> 1;
    const int b_row_off = (lg >> 1) * 8 + lr;
    const int b_chunk_off = lg & 1;

    {
#pragma unroll
        for (int i = 0; i < 2; i++) {
            int idx = tid + 256 * i;
            int r = idx >> 2, c = idx & 3;
            CP16(tile_addr(sa[0], r, c),  Ab + (size_t)r * K + c * 8);
            CP16(tile_addr(sbm[0], r, c), Bb + (size_t)r * K + c * 8);
        }
        CP_COMMIT();
    }

    for (int kt = 0; kt < nk; kt++) {
        const int cur = kt & 1;
        if (kt + 1 < nk) {
            const int nxt = cur ^ 1;
            const __half* Abt = Ab + (kt + 1) * 32;
            const __half* Bbt = Bb + (kt + 1) * 32;
#pragma unroll
            for (int i = 0; i < 2; i++) {
                int idx = tid + 256 * i;
                int r = idx >> 2, c = idx & 3;
                CP16(tile_addr(sa[nxt], r, c),  Abt + (size_t)r * K + c * 8);
                CP16(tile_addr(sbm[nxt], r, c), Bbt + (size_t)r * K + c * 8);
            }
            CP_COMMIT();
            CP_WAIT(1);
        } else {
            CP_WAIT(0);
        }
        __syncthreads();

#pragma unroll
        for (int ks = 0; ks < 2; ks++) {
            uint32_t af[4][4];
#pragma unroll
            for (int mi = 0; mi < 4; mi++) {
                int row = wm * 64 + mi * 16 + a_row_off;
                int chunk = 2 * ks + a_chunk_off;
                ldm_x4(af[mi][0], af[mi][1], af[mi][2], af[mi][3],
                       tile_addr(sa[cur], row, chunk));
            }
            uint32_t bf[4][2];
#pragma unroll
            for (int nj2 = 0; nj2 < 2; nj2++) {
                int row = wn * 32 + nj2 * 16 + b_row_off;
                int chunk = 2 * ks + b_chunk_off;
                uint32_t t0, t1, t2, t3;
                ldm_x4(t0, t1, t2, t3, tile_addr(sbm[cur], row, chunk));
                bf[nj2 * 2][0] = t0; bf[nj2 * 2][1] = t1;
                bf[nj2 * 2 + 1][0] = t2; bf[nj2 * 2 + 1][1] = t3;
            }
#pragma unroll
            for (int mi = 0; mi < 4; mi++)
#pragma unroll
                for (int nj = 0; nj < 4; nj++)
                    mma16816(acc[mi][nj][0], acc[mi][nj][1], acc[mi][nj][2], acc[mi][nj][3],
                             af[mi][0], af[mi][1], af[mi][2], af[mi][3],
                             bf[nj][0], bf[nj][1]);
        }
        __syncthreads();
    }

    const int mrow = lane >> 2;
    const int ncol = (lane & 3) * 2;

    if (mode == 0) {
#pragma unroll
        for (int mi = 0; mi < 4; mi++) {
#pragma unroll
            for (int nj = 0; nj < 4; nj++) {
                size_t r1 = rowBase + wm * 64 + mi * 16 + mrow;
                size_t cc = colBase + wn * 32 + nj * 8 + ncol;
                float2 v0 = make_float2(acc[mi][nj][0], acc[mi][nj][1]);
                float2 v1 = make_float2(acc[mi][nj][2], acc[mi][nj][3]);
                *(float2*)(C + r1 * N + cc) = v0;
                *(float2*)(C + (r1 + 8) * N + cc) = v1;
            }
        }
    } else {
        // scatter fp16 into head-major q/k/v. cc block is uniformly in q, k, or v.
#pragma unroll
        for (int mi = 0; mi < 4; mi++) {
#pragma unroll
            for (int nj = 0; nj < 4; nj++) {
                int r1 = (int)rowBase + wm * 64 + mi * 16 + mrow;   // token row
                int cc = (int)colBase + wn * 32 + nj * 8 + ncol;    // qkv channel
                int bb = r1 >> 11;
                int t  = r1 & (T_ - 1);
                int d  = cc & 63;
                __half* dst;
                if (cc < 1024) {
                    int hh = cc >> 6;
                    dst = g_q16 + ((size_t)(bb * NH + hh) * T_ + t) * HD + d;
                } else if (cc < 1280) {
                    int hh = (cc - 1024) >> 6;
                    dst = g_k16 + ((size_t)(bb * NKV + hh) * T_ + t) * HD + d;
                } else {
                    int hh = (cc - 1280) >> 6;
                    dst = g_v16 + ((size_t)(bb * NKV + hh) * T_ + t) * HD + d;
                }
                __half2 h0 = __floats2half2_rn(acc[mi][nj][0], acc[mi][nj][1]);
                __half2 h1 = __floats2half2_rn(acc[mi][nj][2], acc[mi][nj][3]);
                *(__half2*)dst = h0;
                *(__half2*)(dst + 8 * HD) = h1;    // row r1+8 = token t+8 (same b)
            }
        }
    }
}

// ---------------------------------------------------------------------------
__global__ void f2h(const float* __restrict__ src, __half* __restrict__ dst, int n4)
{
    int i = blockIdx.x * blockDim.x + threadIdx.x;
    if (i >= n4) return;
    float4 v = ((const float4*)src)[i];
    __half2 h0 = __floats2half2_rn(v.x, v.y);
    __half2 h1 = __floats2half2_rn(v.z, v.w);
    uint2 o; o.x = *(uint32_t*)&h0; o.y = *(uint32_t*)&h1;
    ((uint2*)dst)[i] = o;
}

__global__ void pack_w(const float* __restrict__ Wq, const float* __restrict__ Wk,
                       const float* __restrict__ Wv)
{
    int i = blockIdx.x * blockDim.x + threadIdx.x;
    if (i >= QKVC * C_ / 4) return;
    int row = i >> 8;
    int c4 = i & 255;
    const float* src;
    if (row < 1024)      src = Wq + (size_t)row * C_;
    else if (row < 1280) src = Wk + (size_t)(row - 1024) * C_;
    else                 src = Wv + (size_t)(row - 1280) * C_;
    float4 v = ((const float4*)src)[c4];
    __half2 h0 = __floats2half2_rn(v.x, v.y);
    __half2 h1 = __floats2half2_rn(v.z, v.w);
    uint2 o; o.x = *(uint32_t*)&h0; o.y = *(uint32_t*)&h1;
    ((uint2*)(g_wqkv + (size_t)row * C_))[c4] = o;
}

// ---------------------------------------------------------------------------
// RoPE + RMSNorm in-place on fp16 head-major g_q16 (16 heads) / g_k16 (4 heads).
// One warp per (row, unit); 20 units per row. V needs nothing.
// ---------------------------------------------------------------------------
__global__ void rope_rms_ip(const float* __restrict__ cosb, const float* __restrict__ sinb)
{
    int gwarp = (blockIdx.x * blockDim.x + threadIdx.x) >> 5;
    int lane = threadIdx.x & 31;
    const int total = ROWS * (NH + NKV);   // 4096 * 20
    if (gwarp >= total) return;

    int row = gwarp / (NH + NKV);
    int u   = gwarp % (NH + NKV);
    int b = row >> 11;
    int t = row & (T_ - 1);

    __half* base = (u < NH)
        ? g_q16 + ((size_t)(b * NH + u) * T_ + t) * HD
        : g_k16 + ((size_t)(b * NKV + (u - NH)) * T_ + t) * HD;

    float x1 = __half2float(base[lane]);
    float x2 = __half2float(base[lane + 32]);
    float c = cosb[t * 32 + lane];
    float s = sinb[t * 32 + lane];
    float o1 =  x1 * c + x2 * s;
    float o2 = -x1 * s + x2 * c;

    float ss = o1 * o1 + o2 * o2;
#pragma unroll
    for (int off = 16; off; off >>= 1)
        ss += __shfl_xor_sync(0xFFFFFFFFu, ss, off);

    float r = rsqrtf(ss * (1.0f / 64.0f) + 1.1920928955078125e-07f);
    base[lane]      = __float2half_rn(o1 * r);
    base[lane + 32] = __float2half_rn(o2 * r);
}

// ---------------------------------------------------------------------------
// HMMA causal GQA flash attention (R14: split K/V waits; heavy first).
// grid = (T/64, B*NH), block = 128 (4 warps); warp = 16 query rows.
// ---------------------------------------------------------------------------
__global__ void __launch_bounds__(128) flash_mma()
{
    __shared__ __half Qs[64 * 64];
    __shared__ __half Ks[64 * 64];
    __shared__ __half Vs[64 * 64];

    const int tid = threadIdx.x;
    const int lane = tid & 31;
    const int wid = tid >> 5;

    const int bh = blockIdx.y;
    const int b = bh >> 4;
    const int h = bh & 15;
    const int hkv = h >> 2;
    const int qt = (gridDim.x - 1 - blockIdx.x) * 64;   // heavy blocks first

    const __half* qg = g_q16 + ((size_t)(b * NH + h) * T_ + qt) * HD;
    const __half* kg = g_k16 + ((size_t)(b * NKV + hkv) * T_) * HD;
    const __half* vg = g_v16 + ((size_t)(b * NKV + hkv) * T_) * HD;

    const uint32_t sq = smem_u32(Qs), sk = smem_u32(Ks), sv = smem_u32(Vs);

    // stage Q tile (64x64), own commit group
#pragma unroll
    for (int i = 0; i < 4; i++) {
        int idx = tid + 128 * i;      // 0..511
        int r = idx >> 3, c = idx & 7;
        CP16(addr8(sq, r, c), qg + (size_t)r * HD + c * 8);
    }
    CP_COMMIT();

    const int lg = lane >> 3;
    const int lr = lane & 7;
    const int a_row = wid * 16 + (lg & 1) * 8 + lr;   // within Q tile
    const int a_chk = lg >> 1;
    const int b_row = (lg >> 1) * 8 + lr;             // + nb*16 for K
    const int b_chk = lg & 1;                         // + 2*ks
    const int v_row = (lg & 1) * 8 + lr;              // + ks*16 for V (trans)
    const int v_chk = lg >> 1;                        // + 2*jd

    uint32_t aq[4][4];
    bool q_loaded = false;

    float oacc[8][4];
#pragma unroll
    for (int i = 0; i < 8; i++)
#pragma unroll
        for (int j = 0; j < 4; j++) oacc[i][j] = 0.f;

    float mrow0 = -1e30f, mrow1 = -1e30f;
    float lrow0 = 0.f, lrow1 = 0.f;

    const int row_lo = qt + wid * 16 + (lane >> 2);
    const int row_hi = row_lo + 8;
    const float sc = 0.125f;          // 1/sqrt(64)

    for (int kv0 = 0; kv0 <= qt; kv0 += 64) {
        __syncthreads();              // previous iteration done with K/V smem
        // K tile -> group, V tile -> separate group
#pragma unroll
        for (int i = 0; i < 4; i++) {
            int idx = tid + 128 * i;
            int r = idx >> 3, c = idx & 7;
            CP16(addr8(sk, r, c), kg + (size_t)(kv0 + r) * HD + c * 8);
        }
        CP_COMMIT();
#pragma unroll
        for (int i = 0; i < 4; i++) {
            int idx = tid + 128 * i;
            int r = idx >> 3, c = idx & 7;
            CP16(addr8(sv, r, c), vg + (size_t)(kv0 + r) * HD + c * 8);
        }
        CP_COMMIT();

        CP_WAIT(1);                   // Q (first iter) + K complete; V in flight
        __syncthreads();

        if (!q_loaded) {
            q_loaded = true;
#pragma unroll
            for (int ks = 0; ks < 4; ks++)
                ldm_x4(aq[ks][0], aq[ks][1], aq[ks][2], aq[ks][3],
                       addr8(sq, a_row, 2 * ks + a_chk));
        }

        // ---- S = Q K^T ----
        float sacc[8][4];
#pragma unroll
        for (int i = 0; i < 8; i++)
#pragma unroll
            for (int j = 0; j < 4; j++) sacc[i][j] = 0.f;

#pragma unroll
        for (int ks = 0; ks < 4; ks++) {
            uint32_t bf[8][2];
#pragma unroll
            for (int j = 0; j < 4; j++) {
                uint32_t t0, t1, t2, t3;
                ldm_x4(t0, t1, t2, t3, addr8(sk, j * 16 + b_row, 2 * ks + b_chk));
                bf[2 * j][0] = t0; bf[2 * j][1] = t1;
                bf[2 * j + 1][0] = t2; bf[2 * j + 1][1] = t3;
            }
#pragma unroll
            for (int nb = 0; nb < 8; nb++)
                mma16816(sacc[nb][0], sacc[nb][1], sacc[nb][2], sacc[nb][3],
                         aq[ks][0], aq[ks][1], aq[ks][2], aq[ks][3],
                         bf[nb][0], bf[nb][1]);
        }

        // ---- online softmax (V still loading) ----
        const bool diag = (kv0 == qt);
        float mx0 = -1e30f, mx1 = -1e30f;
#pragma unroll
        for (int nb = 0; nb < 8; nb++) {
            float c0 = sacc[nb][0] * sc, c1 = sacc[nb][1] * sc;
            float c2 = sacc[nb][2] * sc, c3 = sacc[nb][3] * sc;
            if (diag) {
                int col = kv0 + nb * 8 + (lane & 3) * 2;
                if (col > row_lo)     c0 = -1e30f;
                if (col + 1 > row_lo) c1 = -1e30f;
                if (col > row_hi)     c2 = -1e30f;
                if (col + 1 > row_hi) c3 = -1e30f;
            }
            sacc[nb][0] = c0; sacc[nb][1] = c1; sacc[nb][2] = c2; sacc[nb][3] = c3;
            mx0 = fmaxf(mx0, fmaxf(c0, c1));
            mx1 = fmaxf(mx1, fmaxf(c2, c3));
        }
        mx0 = fmaxf(mx0, __shfl_xor_sync(0xFFFFFFFFu, mx0, 1));
        mx0 = fmaxf(mx0, __shfl_xor_sync(0xFFFFFFFFu, mx0, 2));
        mx1 = fmaxf(mx1, __shfl_xor_sync(0xFFFFFFFFu, mx1, 1));
        mx1 = fmaxf(mx1, __shfl_xor_sync(0xFFFFFFFFu, mx1, 2));

        float mn0 = fmaxf(mrow0, mx0), mn1 = fmaxf(mrow1, mx1);
        float cor0 = __expf(mrow0 - mn0), cor1 = __expf(mrow1 - mn1);
        mrow0 = mn0; mrow1 = mn1;

        float sum0 = 0.f, sum1 = 0.f;
        uint32_t ph[8][2];
#pragma unroll
        for (int nb = 0; nb < 8; nb++) {
            float p0 = __expf(sacc[nb][0] - mn0);
            float p1 = __expf(sacc[nb][1] - mn0);
            float p2 = __expf(sacc[nb][2] - mn1);
            float p3 = __expf(sacc[nb][3] - mn1);
            sum0 += p0 + p1; sum1 += p2 + p3;
            __half2 h0 = __floats2half2_rn(p0, p1);
            __half2 h1 = __floats2half2_rn(p2, p3);
            ph[nb][0] = *(uint32_t*)&h0;
            ph[nb][1] = *(uint32_t*)&h1;
        }
        lrow0 = lrow0 * cor0 + sum0;
        lrow1 = lrow1 * cor1 + sum1;
#pragma unroll
        for (int nd = 0; nd < 8; nd++) {
            oacc[nd][0] *= cor0; oacc[nd][1] *= cor0;
            oacc[nd][2] *= cor1; oacc[nd][3] *= cor1;
        }

        CP_WAIT(0);                   // V complete
        __syncthreads();

        // ---- O += P V ----
#pragma unroll
        for (int ks = 0; ks < 4; ks++) {
            uint32_t vf[8][2];
#pragma unroll
            for (int jd = 0; jd < 4; jd++) {
                uint32_t t0, t1, t2, t3;
                ldm_x4_t(t0, t1, t2, t3, addr8(sv, ks * 16 + v_row, 2 * jd + v_chk));
                vf[2 * jd][0] = t0; vf[2 * jd][1] = t1;
                vf[2 * jd + 1][0] = t2; vf[2 * jd + 1][1] = t3;
            }
#pragma unroll
            for (int nd = 0; nd < 8; nd++)
                mma16816(oacc[nd][0], oacc[nd][1], oacc[nd][2], oacc[nd][3],
                         ph[2 * ks][0], ph[2 * ks][1], ph[2 * ks + 1][0], ph[2 * ks + 1][1],
                         vf[nd][0], vf[nd][1]);
        }
    }

    // final: reduce l across quad, normalize, store fp16
    lrow0 += __shfl_xor_sync(0xFFFFFFFFu, lrow0, 1);
    lrow0 += __shfl_xor_sync(0xFFFFFFFFu, lrow0, 2);
    lrow1 += __shfl_xor_sync(0xFFFFFFFFu, lrow1, 1);
    lrow1 += __shfl_xor_sync(0xFFFFFFFFu, lrow1, 2);
    float inv0 = 1.f / lrow0, inv1 = 1.f / lrow1;

#pragma unroll
    for (int nd = 0; nd < 8; nd++) {
        int col = nd * 8 + (lane & 3) * 2;
        __half* y0 = g_yh + ((size_t)(b * T_ + row_lo)) * C_ + h * HD + col;
        __half* y1 = g_yh + ((size_t)(b * T_ + row_hi)) * C_ + h * HD + col;
        __half2 h0 = __floats2half2_rn(oacc[nd][0] * inv0, oacc[nd][1] * inv0);
        __half2 h1 = __floats2half2_rn(oacc[nd][2] * inv1, oacc[nd][3] * inv1);
        *(__half2*)y0 = h0;
        *(__half2*)y1 = h1;
    }
}

// ---------------------------------------------------------------------------
extern "C" void kernel_launch(void* const* d_in, const int* in_sizes, int n_in,
                              void* d_out, int out_size)
{
    const float* x    = (const float*)d_in[0];
    const float* cosb = (const float*)d_in[1];
    const float* sinb = (const float*)d_in[2];
    const float* Wq   = (const float*)d_in[3];
    const float* Wk   = (const float*)d_in[4];
    const float* Wv   = (const float*)d_in[5];
    const float* Wo   = (const float*)d_in[6];
    float* out = (float*)d_out;

    __half *xhp, *wop, *yhp, *wqkvp;
    cudaGetSymbolAddress((void**)&xhp,  g_xh);
    cudaGetSymbolAddress((void**)&wop,  g_wo);
    cudaGetSymbolAddress((void**)&yhp,  g_yh);
    cudaGetSymbolAddress((void**)&wqkvp, g_wqkv);

    // conversions
    { int n4 = ROWS * C_ / 4;  f2h<<<(n4 + 255) / 256, 256>>>(x, xhp, n4); }
    { int n4 = QKVC * C_ / 4;  pack_w<<<(n4 + 255) / 256, 256>>>(Wq, Wk, Wv); }
    { int n4 = C_ * C_ / 4;    f2h<<<(n4 + 255) / 256, 256>>>(Wo, wop, n4); }

    // fused QKV projection with direct head-major fp16 scatter epilogue
    gemm_mma<<<dim3(ROWS / 128, QKVC / 128), 256>>>(xhp, wqkvp, out /*unused*/, QKVC, C_, 1);

    // RoPE + RMSNorm in-place on fp16 q/k
    {
        int warps = ROWS * (NH + NKV);
        int threads = warps * 32;
        rope_rms_ip<<<(threads + 255) / 256, 256>>>(cosb, sinb);
    }

    // HMMA causal flash attention
    flash_mma<<<dim3(T_ / 64, B_ * NH), 128>>>();

    // output projection: out[4096,1024] = yh * wo^T (fp32 epilogue)
    gemm_mma<<<dim3(ROWS / 128, C_ / 128), 256>>>(yhp, wop, out, C_, C_, 0);
}

// round 17
// speedup vs baseline: 1.7473x; 1.0781x over previous
#include <cuda_runtime.h>
#include <cuda_fp16.h>
#include <math.h>
#include <cstdint>

#define B_   2
#define T_   2048
#define C_   1024
#define NH   16
#define NKV  4
#define HD   64
#define ROWS (B_ * T_)          // 4096
#define QKVC 1536               // 1024 q + 256 k + 256 v

// ------------------------- scratch (__device__ globals) ---------------------
__device__ __half g_xh[(size_t)ROWS * C_];        // x in fp16
__device__ __half g_wqkv[(size_t)QKVC * C_];      // packed Wq|Wk|Wv fp16
__device__ __half g_wo[(size_t)C_ * C_];          // Wo fp16
__device__ __half g_yh[(size_t)ROWS * C_];        // attention output fp16
__device__ __half g_q16[(size_t)B_ * NH * T_ * HD];   // [b][h][t][d]
__device__ __half g_k16[(size_t)B_ * NKV * T_ * HD];  // [b][hkv][t][d]
__device__ __half g_v16[(size_t)B_ * NKV * T_ * HD];  // [b][hkv][t][d]

// ------------------------------ PTX helpers --------------------------------
__device__ __forceinline__ uint32_t smem_u32(const void* p) {
    uint32_t a;
    asm("{ .reg .u64 t; cvta.to.shared.u64 t, %1; cvt.u32.u64 %0, t; }" : "=r"(a) : "l"(p));
    return a;
}
#define CP16(dst, src) asm volatile("cp.async.cg.shared.global [%0], [%1], 16;" :: "r"(dst), "l"(src) : "memory")
#define CP_COMMIT()    asm volatile("cp.async.commit_group;" ::: "memory")
#define CP_WAIT(n)     asm volatile("cp.async.wait_group %0;" :: "n"(n) : "memory")

__device__ __forceinline__ void ldm_x4(uint32_t& r0, uint32_t& r1, uint32_t& r2, uint32_t& r3,
                                       uint32_t addr) {
    asm volatile("ldmatrix.sync.aligned.m8n8.x4.shared.b16 {%0,%1,%2,%3}, [%4];"
                 : "=r"(r0), "=r"(r1), "=r"(r2), "=r"(r3) : "r"(addr));
}
__device__ __forceinline__ void ldm_x4_t(uint32_t& r0, uint32_t& r1, uint32_t& r2, uint32_t& r3,
                                         uint32_t addr) {
    asm volatile("ldmatrix.sync.aligned.m8n8.x4.trans.shared.b16 {%0,%1,%2,%3}, [%4];"
                 : "=r"(r0), "=r"(r1), "=r"(r2), "=r"(r3) : "r"(addr));
}
__device__ __forceinline__ void mma16816(float& c0, float& c1, float& c2, float& c3,
                                         uint32_t a0, uint32_t a1, uint32_t a2, uint32_t a3,
                                         uint32_t b0, uint32_t b1) {
    asm volatile("mma.sync.aligned.m16n8k16.row.col.f32.f16.f16.f32 "
                 "{%0,%1,%2,%3}, {%4,%5,%6,%7}, {%8,%9}, {%0,%1,%2,%3};"
                 : "+f"(c0), "+f"(c1), "+f"(c2), "+f"(c3)
                 : "r"(a0), "r"(a1), "r"(a2), "r"(a3), "r"(b0), "r"(b1));
}

// 128B-row tile (64 halves, 8 chunks of 16B). chunk ^= row&7. (flash-proven)
__device__ __forceinline__ uint32_t addr8(uint32_t base, int r, int c) {
    return base + (uint32_t)(r * 128) + (uint32_t)((c ^ (r & 7)) * 16);
}

// ---------------------------------------------------------------------------
// HMMA fp16 GEMM: C[M,N] = A[M,K] * B[N,K]^T.
// BM=BN=128, BK=64, 256 threads, 8 warps (2x4), warp tile 64x32, 2-stage.
// Dynamic smem 64 KB: stage s: A at s*32768, B at s*32768+16384.
// mode 0: fp32 C out. mode 1: scatter fp16 into head-major g_q16/g_k16/g_v16.
// ---------------------------------------------------------------------------
__global__ void __launch_bounds__(256) gemm_mma(
    const __half* __restrict__ A, const __half* __restrict__ Bm,
    float* __restrict__ C, int N, int K, int mode)
{
    extern __shared__ char dynsmem[];
    const uint32_t base = smem_u32(dynsmem);

    const int tid = threadIdx.x;
    const int lane = tid & 31;
    const int wid = tid >> 5;
    const int wm = wid >> 2;
    const int wn = wid & 3;

    const size_t rowBase = (size_t)blockIdx.x * 128;
    const size_t colBase = (size_t)blockIdx.y * 128;
    const __half* Ab = A + rowBase * K;
    const __half* Bb = Bm + colBase * K;

    const uint32_t sa[2]  = { base, base + 32768 };
    const uint32_t sbm[2] = { base + 16384, base + 32768 + 16384 };

    float acc[4][4][4];
#pragma unroll
    for (int i = 0; i < 4; i++)
#pragma unroll
        for (int j = 0; j < 4; j++)
#pragma unroll
            for (int q = 0; q < 4; q++) acc[i][j][q] = 0.f;

    const int nk = K >> 6;            // K / 64

    const int lg = lane >> 3;
    const int lr = lane & 7;
    const int a_row_off = (lg & 1) * 8 + lr;    // + wm*64 + mi*16
    const int a_chunk_off = lg >> 1;            // + 2*ks
    const int b_row_off = (lg >> 1) * 8 + lr;   // + wn*32 + nj2*16
    const int b_chunk_off = lg & 1;             // + 2*ks

    // prologue: stage 0 (128 rows x 8 chunks per matrix, 4 chunks/thread each)
    {
#pragma unroll
        for (int i = 0; i < 4; i++) {
            int idx = tid + 256 * i;          // 0..1023
            int r = idx >> 3, c = idx & 7;
            CP16(addr8(sa[0], r, c),  Ab + (size_t)r * K + c * 8);
            CP16(addr8(sbm[0], r, c), Bb + (size_t)r * K + c * 8);
        }
        CP_COMMIT();
    }

    for (int kt = 0; kt < nk; kt++) {
        const int cur = kt & 1;
        if (kt + 1 < nk) {
            const int nxt = cur ^ 1;
            const __half* Abt = Ab + (kt + 1) * 64;
            const __half* Bbt = Bb + (kt + 1) * 64;
#pragma unroll
            for (int i = 0; i < 4; i++) {
                int idx = tid + 256 * i;
                int r = idx >> 3, c = idx & 7;
                CP16(addr8(sa[nxt], r, c),  Abt + (size_t)r * K + c * 8);
                CP16(addr8(sbm[nxt], r, c), Bbt + (size_t)r * K + c * 8);
            }
            CP_COMMIT();
            CP_WAIT(1);
        } else {
            CP_WAIT(0);
        }
        __syncthreads();

#pragma unroll
        for (int ks = 0; ks < 4; ks++) {
            uint32_t af[4][4];
#pragma unroll
            for (int mi = 0; mi < 4; mi++) {
                int row = wm * 64 + mi * 16 + a_row_off;
                ldm_x4(af[mi][0], af[mi][1], af[mi][2], af[mi][3],
                       addr8(sa[cur], row, 2 * ks + a_chunk_off));
            }
            uint32_t bf[4][2];
#pragma unroll
            for (int nj2 = 0; nj2 < 2; nj2++) {
                int row = wn * 32 + nj2 * 16 + b_row_off;
                uint32_t t0, t1, t2, t3;
                ldm_x4(t0, t1, t2, t3, addr8(sbm[cur], row, 2 * ks + b_chunk_off));
                bf[nj2 * 2][0] = t0; bf[nj2 * 2][1] = t1;
                bf[nj2 * 2 + 1][0] = t2; bf[nj2 * 2 + 1][1] = t3;
            }
#pragma unroll
            for (int mi = 0; mi < 4; mi++)
#pragma unroll
                for (int nj = 0; nj < 4; nj++)
                    mma16816(acc[mi][nj][0], acc[mi][nj][1], acc[mi][nj][2], acc[mi][nj][3],
                             af[mi][0], af[mi][1], af[mi][2], af[mi][3],
                             bf[nj][0], bf[nj][1]);
        }
        __syncthreads();
    }

    const int mrow = lane >> 2;
    const int ncol = (lane & 3) * 2;

    if (mode == 0) {
#pragma unroll
        for (int mi = 0; mi < 4; mi++) {
#pragma unroll
            for (int nj = 0; nj < 4; nj++) {
                size_t r1 = rowBase + wm * 64 + mi * 16 + mrow;
                size_t cc = colBase + wn * 32 + nj * 8 + ncol;
                float2 v0 = make_float2(acc[mi][nj][0], acc[mi][nj][1]);
                float2 v1 = make_float2(acc[mi][nj][2], acc[mi][nj][3]);
                *(float2*)(C + r1 * N + cc) = v0;
                *(float2*)(C + (r1 + 8) * N + cc) = v1;
            }
        }
    } else {
        // scatter fp16 into head-major q/k/v
#pragma unroll
        for (int mi = 0; mi < 4; mi++) {
#pragma unroll
            for (int nj = 0; nj < 4; nj++) {
                int r1 = (int)rowBase + wm * 64 + mi * 16 + mrow;   // token row
                int cc = (int)colBase + wn * 32 + nj * 8 + ncol;    // qkv channel
                int bb = r1 >> 11;
                int t  = r1 & (T_ - 1);
                int d  = cc & 63;
                __half* dst;
                if (cc < 1024) {
                    int hh = cc >> 6;
                    dst = g_q16 + ((size_t)(bb * NH + hh) * T_ + t) * HD + d;
                } else if (cc < 1280) {
                    int hh = (cc - 1024) >> 6;
                    dst = g_k16 + ((size_t)(bb * NKV + hh) * T_ + t) * HD + d;
                } else {
                    int hh = (cc - 1280) >> 6;
                    dst = g_v16 + ((size_t)(bb * NKV + hh) * T_ + t) * HD + d;
                }
                __half2 h0 = __floats2half2_rn(acc[mi][nj][0], acc[mi][nj][1]);
                __half2 h1 = __floats2half2_rn(acc[mi][nj][2], acc[mi][nj][3]);
                *(__half2*)dst = h0;
                *(__half2*)(dst + 8 * HD) = h1;    // row r1+8 = token t+8
            }
        }
    }
}

// ---------------------------------------------------------------------------
// One fused conversion kernel: x->fp16, pack Wq|Wk|Wv->fp16, Wo->fp16.
// float4 index space: [0, 1048576) x, [1048576, 1441792) wqkv, then wo.
// ---------------------------------------------------------------------------
#define N4_X  (ROWS * C_ / 4)          // 1048576
#define N4_W  (QKVC * C_ / 4)          // 393216
#define N4_O  (C_ * C_ / 4)            // 262144
__global__ void prep(const float* __restrict__ x,
                     const float* __restrict__ Wq, const float* __restrict__ Wk,
                     const float* __restrict__ Wv, const float* __restrict__ Wo)
{
    int i = blockIdx.x * blockDim.x + threadIdx.x;
    const float* src;
    __half* dst;
    int j;
    if (i < N4_X) {
        j = i;
        src = x;
        dst = g_xh;
    } else if (i < N4_X + N4_W) {
        j = i - N4_X;
        int row = j >> 8;            // /256
        int c4 = j & 255;
        const float* s;
        if (row < 1024)      s = Wq + (size_t)row * C_;
        else if (row < 1280) s = Wk + (size_t)(row - 1024) * C_;
        else                 s = Wv + (size_t)(row - 1280) * C_;
        float4 v = ((const float4*)s)[c4];
        __half2 h0 = __floats2half2_rn(v.x, v.y);
        __half2 h1 = __floats2half2_rn(v.z, v.w);
        uint2 o; o.x = *(uint32_t*)&h0; o.y = *(uint32_t*)&h1;
        ((uint2*)(g_wqkv + (size_t)row * C_))[c4] = o;
        return;
    } else if (i < N4_X + N4_W + N4_O) {
        j = i - N4_X - N4_W;
        src = Wo;
        dst = g_wo;
    } else {
        return;
    }
    float4 v = ((const float4*)src)[j];
    __half2 h0 = __floats2half2_rn(v.x, v.y);
    __half2 h1 = __floats2half2_rn(v.z, v.w);
    uint2 o; o.x = *(uint32_t*)&h0; o.y = *(uint32_t*)&h1;
    ((uint2*)dst)[j] = o;
}

// ---------------------------------------------------------------------------
// RoPE + RMSNorm in-place on fp16 head-major g_q16 (16 heads) / g_k16 (4 heads).
// ---------------------------------------------------------------------------
__global__ void rope_rms_ip(const float* __restrict__ cosb, const float* __restrict__ sinb)
{
    int gwarp = (blockIdx.x * blockDim.x + threadIdx.x) >> 5;
    int lane = threadIdx.x & 31;
    const int total = ROWS * (NH + NKV);   // 4096 * 20
    if (gwarp >= total) return;

    int row = gwarp / (NH + NKV);
    int u   = gwarp % (NH + NKV);
    int b = row >> 11;
    int t = row & (T_ - 1);

    __half* base = (u < NH)
        ? g_q16 + ((size_t)(b * NH + u) * T_ + t) * HD
        : g_k16 + ((size_t)(b * NKV + (u - NH)) * T_ + t) * HD;

    float x1 = __half2float(base[lane]);
    float x2 = __half2float(base[lane + 32]);
    float c = cosb[t * 32 + lane];
    float s = sinb[t * 32 + lane];
    float o1 =  x1 * c + x2 * s;
    float o2 = -x1 * s + x2 * c;

    float ss = o1 * o1 + o2 * o2;
#pragma unroll
    for (int off = 16; off; off >>= 1)
        ss += __shfl_xor_sync(0xFFFFFFFFu, ss, off);

    float r = rsqrtf(ss * (1.0f / 64.0f) + 1.1920928955078125e-07f);
    base[lane]      = __float2half_rn(o1 * r);
    base[lane + 32] = __float2half_rn(o2 * r);
}

// ---------------------------------------------------------------------------
// HMMA causal GQA flash attention (R14/R15 validated: split K/V waits; heavy first).
// grid = (T/64, B*NH), block = 128 (4 warps); warp = 16 query rows.
// ---------------------------------------------------------------------------
__global__ void __launch_bounds__(128) flash_mma()
{
    __shared__ __half Qs[64 * 64];
    __shared__ __half Ks[64 * 64];
    __shared__ __half Vs[64 * 64];

    const int tid = threadIdx.x;
    const int lane = tid & 31;
    const int wid = tid >> 5;

    const int bh = blockIdx.y;
    const int b = bh >> 4;
    const int h = bh & 15;
    const int hkv = h >> 2;
    const int qt = (gridDim.x - 1 - blockIdx.x) * 64;   // heavy blocks first

    const __half* qg = g_q16 + ((size_t)(b * NH + h) * T_ + qt) * HD;
    const __half* kg = g_k16 + ((size_t)(b * NKV + hkv) * T_) * HD;
    const __half* vg = g_v16 + ((size_t)(b * NKV + hkv) * T_) * HD;

    const uint32_t sq = smem_u32(Qs), sk = smem_u32(Ks), sv = smem_u32(Vs);

    // stage Q tile (64x64), own commit group
#pragma unroll
    for (int i = 0; i < 4; i++) {
        int idx = tid + 128 * i;      // 0..511
        int r = idx >> 3, c = idx & 7;
        CP16(addr8(sq, r, c), qg + (size_t)r * HD + c * 8);
    }
    CP_COMMIT();

    const int lg = lane >> 3;
    const int lr = lane & 7;
    const int a_row = wid * 16 + (lg & 1) * 8 + lr;   // within Q tile
    const int a_chk = lg >> 1;
    const int b_row = (lg >> 1) * 8 + lr;             // + nb*16 for K
    const int b_chk = lg & 1;                         // + 2*ks
    const int v_row = (lg & 1) * 8 + lr;              // + ks*16 for V (trans)
    const int v_chk = lg >> 1;                        // + 2*jd

    uint32_t aq[4][4];
    bool q_loaded = false;

    float oacc[8][4];
#pragma unroll
    for (int i = 0; i < 8; i++)
#pragma unroll
        for (int j = 0; j < 4; j++) oacc[i][j] = 0.f;

    float mrow0 = -1e30f, mrow1 = -1e30f;
    float lrow0 = 0.f, lrow1 = 0.f;

    const int row_lo = qt + wid * 16 + (lane >> 2);
    const int row_hi = row_lo + 8;
    const float sc = 0.125f;          // 1/sqrt(64)

    for (int kv0 = 0; kv0 <= qt; kv0 += 64) {
        __syncthreads();              // previous iteration done with K/V smem
        // K tile -> group, V tile -> separate group
#pragma unroll
        for (int i = 0; i < 4; i++) {
            int idx = tid + 128 * i;
            int r = idx >> 3, c = idx & 7;
            CP16(addr8(sk, r, c), kg + (size_t)(kv0 + r) * HD + c * 8);
        }
        CP_COMMIT();
#pragma unroll
        for (int i = 0; i < 4; i++) {
            int idx = tid + 128 * i;
            int r = idx >> 3, c = idx & 7;
            CP16(addr8(sv, r, c), vg + (size_t)(kv0 + r) * HD + c * 8);
        }
        CP_COMMIT();

        CP_WAIT(1);                   // Q (first iter) + K complete; V in flight
        __syncthreads();

        if (!q_loaded) {
            q_loaded = true;
#pragma unroll
            for (int ks = 0; ks < 4; ks++)
                ldm_x4(aq[ks][0], aq[ks][1], aq[ks][2], aq[ks][3],
                       addr8(sq, a_row, 2 * ks + a_chk));
        }

        // ---- S = Q K^T ----
        float sacc[8][4];
#pragma unroll
        for (int i = 0; i < 8; i++)
#pragma unroll
            for (int j = 0; j < 4; j++) sacc[i][j] = 0.f;

#pragma unroll
        for (int ks = 0; ks < 4; ks++) {
            uint32_t bf[8][2];
#pragma unroll
            for (int j = 0; j < 4; j++) {
                uint32_t t0, t1, t2, t3;
                ldm_x4(t0, t1, t2, t3, addr8(sk, j * 16 + b_row, 2 * ks + b_chk));
                bf[2 * j][0] = t0; bf[2 * j][1] = t1;
                bf[2 * j + 1][0] = t2; bf[2 * j + 1][1] = t3;
            }
#pragma unroll
            for (int nb = 0; nb < 8; nb++)
                mma16816(sacc[nb][0], sacc[nb][1], sacc[nb][2], sacc[nb][3],
                         aq[ks][0], aq[ks][1], aq[ks][2], aq[ks][3],
                         bf[nb][0], bf[nb][1]);
        }

        // ---- online softmax (V still loading) ----
        const bool diag = (kv0 == qt);
        float mx0 = -1e30f, mx1 = -1e30f;
#pragma unroll
        for (int nb = 0; nb < 8; nb++) {
            float c0 = sacc[nb][0] * sc, c1 = sacc[nb][1] * sc;
            float c2 = sacc[nb][2] * sc, c3 = sacc[nb][3] * sc;
            if (diag) {
                int col = kv0 + nb * 8 + (lane & 3) * 2;
                if (col > row_lo)     c0 = -1e30f;
                if (col + 1 > row_lo) c1 = -1e30f;
                if (col > row_hi)     c2 = -1e30f;
                if (col + 1 > row_hi) c3 = -1e30f;
            }
            sacc[nb][0] = c0; sacc[nb][1] = c1; sacc[nb][2] = c2; sacc[nb][3] = c3;
            mx0 = fmaxf(mx0, fmaxf(c0, c1));
            mx1 = fmaxf(mx1, fmaxf(c2, c3));
        }
        mx0 = fmaxf(mx0, __shfl_xor_sync(0xFFFFFFFFu, mx0, 1));
        mx0 = fmaxf(mx0, __shfl_xor_sync(0xFFFFFFFFu, mx0, 2));
        mx1 = fmaxf(mx1, __shfl_xor_sync(0xFFFFFFFFu, mx1, 1));
        mx1 = fmaxf(mx1, __shfl_xor_sync(0xFFFFFFFFu, mx1, 2));

        float mn0 = fmaxf(mrow0, mx0), mn1 = fmaxf(mrow1, mx1);
        float cor0 = __expf(mrow0 - mn0), cor1 = __expf(mrow1 - mn1);
        mrow0 = mn0; mrow1 = mn1;

        float sum0 = 0.f, sum1 = 0.f;
        uint32_t ph[8][2];
#pragma unroll
        for (int nb = 0; nb < 8; nb++) {
            float p0 = __expf(sacc[nb][0] - mn0);
            float p1 = __expf(sacc[nb][1] - mn0);
            float p2 = __expf(sacc[nb][2] - mn1);
            float p3 = __expf(sacc[nb][3] - mn1);
            sum0 += p0 + p1; sum1 += p2 + p3;
            __half2 h0 = __floats2half2_rn(p0, p1);
            __half2 h1 = __floats2half2_rn(p2, p3);
            ph[nb][0] = *(uint32_t*)&h0;
            ph[nb][1] = *(uint32_t*)&h1;
        }
        lrow0 = lrow0 * cor0 + sum0;
        lrow1 = lrow1 * cor1 + sum1;
#pragma unroll
        for (int nd = 0; nd < 8; nd++) {
            oacc[nd][0] *= cor0; oacc[nd][1] *= cor0;
            oacc[nd][2] *= cor1; oacc[nd][3] *= cor1;
        }

        CP_WAIT(0);                   // V complete
        __syncthreads();

        // ---- O += P V ----
#pragma unroll
        for (int ks = 0; ks < 4; ks++) {
            uint32_t vf[8][2];
#pragma unroll
            for (int jd = 0; jd < 4; jd++) {
                uint32_t t0, t1, t2, t3;
                ldm_x4_t(t0, t1, t2, t3, addr8(sv, ks * 16 + v_row, 2 * jd + v_chk));
                vf[2 * jd][0] = t0; vf[2 * jd][1] = t1;
                vf[2 * jd + 1][0] = t2; vf[2 * jd + 1][1] = t3;
            }
#pragma unroll
            for (int nd = 0; nd < 8; nd++)
                mma16816(oacc[nd][0], oacc[nd][1], oacc[nd][2], oacc[nd][3],
                         ph[2 * ks][0], ph[2 * ks][1], ph[2 * ks + 1][0], ph[2 * ks + 1][1],
                         vf[nd][0], vf[nd][1]);
        }
    }

    // final: reduce l across quad, normalize, store fp16
    lrow0 += __shfl_xor_sync(0xFFFFFFFFu, lrow0, 1);
    lrow0 += __shfl_xor_sync(0xFFFFFFFFu, lrow0, 2);
    lrow1 += __shfl_xor_sync(0xFFFFFFFFu, lrow1, 1);
    lrow1 += __shfl_xor_sync(0xFFFFFFFFu, lrow1, 2);
    float inv0 = 1.f / lrow0, inv1 = 1.f / lrow1;

#pragma unroll
    for (int nd = 0; nd < 8; nd++) {
        int col = nd * 8 + (lane & 3) * 2;
        __half* y0 = g_yh + ((size_t)(b * T_ + row_lo)) * C_ + h * HD + col;
        __half* y1 = g_yh + ((size_t)(b * T_ + row_hi)) * C_ + h * HD + col;
        __half2 h0 = __floats2half2_rn(oacc[nd][0] * inv0, oacc[nd][1] * inv0);
        __half2 h1 = __floats2half2_rn(oacc[nd][2] * inv1, oacc[nd][3] * inv1);
        *(__half2*)y0 = h0;
        *(__half2*)y1 = h1;
    }
}

// ---------------------------------------------------------------------------
extern "C" void kernel_launch(void* const* d_in, const int* in_sizes, int n_in,
                              void* d_out, int out_size)
{
    const float* x    = (const float*)d_in[0];
    const float* cosb = (const float*)d_in[1];
    const float* sinb = (const float*)d_in[2];
    const float* Wq   = (const float*)d_in[3];
    const float* Wk   = (const float*)d_in[4];
    const float* Wv   = (const float*)d_in[5];
    const float* Wo   = (const float*)d_in[6];
    float* out = (float*)d_out;

    __half *xhp, *wop, *yhp, *wqkvp;
    cudaGetSymbolAddress((void**)&xhp,  g_xh);
    cudaGetSymbolAddress((void**)&wop,  g_wo);
    cudaGetSymbolAddress((void**)&yhp,  g_yh);
    cudaGetSymbolAddress((void**)&wqkvp, g_wqkv);

    cudaFuncSetAttribute(gemm_mma, cudaFuncAttributeMaxDynamicSharedMemorySize, 65536);

    // fused conversions (x, Wqkv pack, Wo)
    {
        int n4 = N4_X + N4_W + N4_O;
        prep<<<(n4 + 255) / 256, 256>>>(x, Wq, Wk, Wv, Wo);
    }

    // fused QKV projection with direct head-major fp16 scatter epilogue
    gemm_mma<<<dim3(ROWS / 128, QKVC / 128), 256, 65536>>>(xhp, wqkvp, out /*unused*/, QKVC, C_, 1);

    // RoPE + RMSNorm in-place on fp16 q/k
    {
        int warps = ROWS * (NH + NKV);
        int threads = warps * 32;
        rope_rms_ip<<<(threads + 255) / 256, 256>>>(cosb, sinb);
    }

    // HMMA causal flash attention
    flash_mma<<<dim3(T_ / 64, B_ * NH), 128>>>();

    // output projection: out[4096,1024] = yh * wo^T (fp32 epilogue)
    gemm_mma<<<dim3(ROWS / 128, C_ / 128), 256, 65536>>>(yhp, wop, out, C_, C_, 0);
}